// round 4
// baseline (speedup 1.0000x reference)
#include <cuda_runtime.h>
#include <math.h>
#include <stdint.h>

// ---------------------------------------------------------------------------
// Problem constants
// ---------------------------------------------------------------------------
#define NLAYERS 4
#define NB      4
#define SQ      512
#define DM      512
#define NH      8
#define DH      64
#define MEMN    512
#define CMEMN   128
#define RRATIO  4
#define LLAT    256
#define FFD     2048
#define KVN     (CMEMN + MEMN + SQ)   // 1152
#define MROWS   (NB * SQ)             // 2048

// ---------------------------------------------------------------------------
// Scratch (device globals: allowed; no runtime allocation)
// ---------------------------------------------------------------------------
__device__ float g_x  [MROWS * DM];
__device__ float g_kv [NB * KVN * DM];
__device__ float g_q  [MROWS * DM];
__device__ float g_k  [NB * KVN * DM];
__device__ float g_v  [NB * KVN * DM];
__device__ float g_dots[(size_t)NB * NH * SQ * KVN];
__device__ float g_pos [(size_t)NB * NH * SQ * KVN];
__device__ float g_ao [MROWS * DM];
__device__ float g_t1 [MROWS * DM];
__device__ float g_t2 [MROWS * DM];
__device__ float g_cm [NB * CMEMN * DM];
__device__ float g_kcm[NB * CMEMN * DM];
__device__ float g_vcm[NB * CMEMN * DM];
__device__ float g_y  [MROWS * DM];
__device__ float g_ff [MROWS * FFD];
__device__ float g_wc [NLAYERS * RRATIO * DM * DM];
__device__ float g_part[NLAYERS * 128];

// ---------------------------------------------------------------------------
// Generic SGEMM: C[M,N] = A[M,K] @ B[K,N] (+ epilogue)
// BM=128, BN=64, BK=16, 256 threads, 8x4 per thread.
// EPI: 0 none, 1 +resid, 2 +bias, 3 gelu(.+bias), 4 +bias+resid
// ---------------------------------------------------------------------------
template<int EPI>
__global__ __launch_bounds__(256) void sgemm_k(
    const float* __restrict__ A, const float* __restrict__ Bw,
    float* __restrict__ C, int M, int N, int K,
    const float* __restrict__ bias, const float* __restrict__ resid)
{
    __shared__ __align__(16) float As[16][132];
    __shared__ __align__(16) float Bs[16][64];
    const int tid  = threadIdx.x;
    const int tx   = tid & 15, ty = tid >> 4;
    const int row0 = blockIdx.y * 128, col0 = blockIdx.x * 64;
    const int ar   = tid >> 2,  ak = (tid & 3) << 2;
    const int br   = tid >> 4,  bc = (tid & 15) << 2;
    const float* Ag = A + (size_t)row0 * K;
    const float* Bg = Bw + col0;

    float acc[8][4] = {};
    for (int k0 = 0; k0 < K; k0 += 16) {
        float4 a0 = *(const float4*)(Ag + (size_t)ar        * K + k0 + ak);
        float4 a1 = *(const float4*)(Ag + (size_t)(ar + 64) * K + k0 + ak);
        float4 b0 = *(const float4*)(Bg + (size_t)(k0 + br) * N + bc);
        As[ak+0][ar]    = a0.x; As[ak+1][ar]    = a0.y; As[ak+2][ar]    = a0.z; As[ak+3][ar]    = a0.w;
        As[ak+0][ar+64] = a1.x; As[ak+1][ar+64] = a1.y; As[ak+2][ar+64] = a1.z; As[ak+3][ar+64] = a1.w;
        *(float4*)&Bs[br][bc] = b0;
        __syncthreads();
#pragma unroll
        for (int k = 0; k < 16; k++) {
            float4 a0v = *(const float4*)&As[k][ty*8];
            float4 a1v = *(const float4*)&As[k][ty*8 + 4];
            float4 bv  = *(const float4*)&Bs[k][tx*4];
            float am[8] = {a0v.x,a0v.y,a0v.z,a0v.w,a1v.x,a1v.y,a1v.z,a1v.w};
            float bn[4] = {bv.x,bv.y,bv.z,bv.w};
#pragma unroll
            for (int m = 0; m < 8; m++)
#pragma unroll
                for (int n = 0; n < 4; n++) acc[m][n] += am[m] * bn[n];
        }
        __syncthreads();
    }
#pragma unroll
    for (int m = 0; m < 8; m++) {
        const int r = row0 + ty*8 + m;
#pragma unroll
        for (int n = 0; n < 4; n++) {
            const int c = col0 + tx*4 + n;
            float vv = acc[m][n];
            if (EPI == 1) vv += resid[(size_t)r * N + c];
            if (EPI == 2) vv += bias[c];
            if (EPI == 3) { vv += bias[c]; vv = 0.5f * vv * (1.0f + erff(vv * 0.70710678118654752440f)); }
            if (EPI == 4) vv += bias[c] + resid[(size_t)r * N + c];
            C[(size_t)r * N + c] = vv;
        }
    }
}

// ---------------------------------------------------------------------------
// Attention scores: out[bh, i, j] = scale * sum_d Q[b,i,h,d] * Kb[...,j,d]
// Q layout (B,S,D) with head column offset. Kb addressed via strides so the
// same kernel serves K-projections and pos_emb.
// Block: 64 queries x 64 keys, full DH=64 k-pass. 256 threads, 4x4/thread.
// ---------------------------------------------------------------------------
__global__ __launch_bounds__(256) void scores_k(
    const float* __restrict__ Q, const float* __restrict__ Kb,
    float* __restrict__ out, int L, int ldb, long bSB, long bSH, float scale)
{
    __shared__ __align__(16) float Qs[64][68];  // [d][i]
    __shared__ __align__(16) float Ks[64][68];  // [d][j]
    const int bh = blockIdx.z, b = bh >> 3, h = bh & 7;
    const int i0 = blockIdx.y * 64, j0 = blockIdx.x * 64;
    const float* Qg = Q + ((size_t)(b * SQ + i0)) * DM + h * DH;
    const float* Kg = Kb + (size_t)b * bSB + (size_t)h * bSH + (size_t)j0 * ldb;
    const int tid = threadIdx.x;
    const int rr = tid >> 4, c4 = (tid & 15) << 2;
#pragma unroll
    for (int s = 0; s < 4; s++) {
        const int r = rr + s * 16;
        float4 qv = *(const float4*)(Qg + (size_t)r * DM + c4);
        Qs[c4+0][r] = qv.x; Qs[c4+1][r] = qv.y; Qs[c4+2][r] = qv.z; Qs[c4+3][r] = qv.w;
        float4 kv2 = *(const float4*)(Kg + (size_t)r * ldb + c4);
        Ks[c4+0][r] = kv2.x; Ks[c4+1][r] = kv2.y; Ks[c4+2][r] = kv2.z; Ks[c4+3][r] = kv2.w;
    }
    __syncthreads();
    const int tx = tid & 15, ty = tid >> 4;
    float acc[4][4] = {};
#pragma unroll
    for (int d = 0; d < 64; d++) {
        float4 av = *(const float4*)&Qs[d][ty*4];
        float4 bv = *(const float4*)&Ks[d][tx*4];
        float am[4] = {av.x, av.y, av.z, av.w};
        float bn[4] = {bv.x, bv.y, bv.z, bv.w};
#pragma unroll
        for (int m = 0; m < 4; m++)
#pragma unroll
            for (int n = 0; n < 4; n++) acc[m][n] += am[m] * bn[n];
    }
    float* Og = out + ((long)bh * SQ + i0) * (long)L + j0;
#pragma unroll
    for (int m = 0; m < 4; m++)
#pragma unroll
        for (int n = 0; n < 4; n++)
            Og[(long)(ty*4 + m) * L + tx*4 + n] = acc[m][n] * scale;
}

// ---------------------------------------------------------------------------
// AV: out[b,i,h,d] = sum_j P[bh,i,j] * V[b,j,h,d]    (out in (B,S,H*DH))
// ---------------------------------------------------------------------------
__global__ __launch_bounds__(256) void av_k(
    const float* __restrict__ P, const float* __restrict__ V,
    float* __restrict__ out, int L)
{
    __shared__ __align__(16) float Ps[64][68];  // [j][i]
    __shared__ __align__(16) float Vs[64][68];  // [j][d]
    const int bh = blockIdx.z, b = bh >> 3, h = bh & 7;
    const int i0 = blockIdx.y * 64;
    const float* Pg = P + ((long)bh * SQ + i0) * (long)L;
    const float* Vg = V + (size_t)b * L * DM + h * DH;
    const int tid = threadIdx.x;
    const int rr = tid >> 4, c4 = (tid & 15) << 2;
    const int tx = tid & 15, ty = tid >> 4;
    float acc[4][4] = {};
    for (int j0 = 0; j0 < L; j0 += 64) {
#pragma unroll
        for (int s = 0; s < 4; s++) {
            const int r = rr + s * 16;
            float4 pv = *(const float4*)(Pg + (long)r * L + j0 + c4);
            Ps[c4+0][r] = pv.x; Ps[c4+1][r] = pv.y; Ps[c4+2][r] = pv.z; Ps[c4+3][r] = pv.w;
            float4 vv = *(const float4*)(Vg + (size_t)(j0 + r) * DM + c4);
            *(float4*)&Vs[r][c4] = vv;
        }
        __syncthreads();
#pragma unroll
        for (int j = 0; j < 64; j++) {
            float4 av = *(const float4*)&Ps[j][ty*4];
            float4 bv = *(const float4*)&Vs[j][tx*4];
            float am[4] = {av.x, av.y, av.z, av.w};
            float bn[4] = {bv.x, bv.y, bv.z, bv.w};
#pragma unroll
            for (int m = 0; m < 4; m++)
#pragma unroll
                for (int n = 0; n < 4; n++) acc[m][n] += am[m] * bn[n];
        }
        __syncthreads();
    }
    float* Og = out + ((size_t)(b * SQ + i0)) * DM + h * DH;
#pragma unroll
    for (int m = 0; m < 4; m++)
#pragma unroll
        for (int n = 0; n < 4; n++)
            Og[(size_t)(ty*4 + m) * DM + tx*4 + n] = acc[m][n];
}

// ---------------------------------------------------------------------------
// Softmax over row of length L (multiple of 128), optional shifted pos add:
//   val[j] += posR[bh,i, j + S-1 - i]  when index < KV  (the shift() gather)
// ---------------------------------------------------------------------------
__global__ __launch_bounds__(128) void softmax_k(
    float* __restrict__ dots, const float* __restrict__ posR, int L, int usePos)
{
    const int i = blockIdx.x, bh = blockIdx.y;
    float* row = dots + ((long)bh * SQ + i) * (long)L;
    const float* prow = posR + ((long)bh * SQ + i) * (long)KVN;
    const int tid = threadIdx.x;
    const int nper = L >> 7;
    float vals[9];
    float mx = -1e30f;
    for (int t = 0; t < nper; t++) {
        const int j = tid + t * 128;
        float vv = row[j];
        if (usePos) {
            const int jp = j + (SQ - 1) - i;
            if (jp < KVN) vv += prow[jp];
        }
        vals[t] = vv;
        mx = fmaxf(mx, vv);
    }
    __shared__ float sh[128];
    sh[tid] = mx; __syncthreads();
    for (int o = 64; o > 0; o >>= 1) { if (tid < o) sh[tid] = fmaxf(sh[tid], sh[tid + o]); __syncthreads(); }
    mx = sh[0]; __syncthreads();
    float s = 0.f;
    for (int t = 0; t < nper; t++) { vals[t] = expf(vals[t] - mx); s += vals[t]; }
    sh[tid] = s; __syncthreads();
    for (int o = 64; o > 0; o >>= 1) { if (tid < o) sh[tid] += sh[tid + o]; __syncthreads(); }
    const float inv = 1.0f / sh[0];
    for (int t = 0; t < nper; t++) row[tid + t * 128] = vals[t] * inv;
}

// ---------------------------------------------------------------------------
// LayerNorm over D=512, eps=1e-5. One block (128 thr) per row.
// ---------------------------------------------------------------------------
__global__ __launch_bounds__(128) void ln_k(
    const float* __restrict__ x, const float* __restrict__ g,
    const float* __restrict__ bt, float* __restrict__ out)
{
    const int row = blockIdx.x, tid = threadIdx.x;
    const float* xr = x + (size_t)row * DM;
    float v[4]; float s = 0.f, s2 = 0.f;
#pragma unroll
    for (int t = 0; t < 4; t++) { v[t] = xr[tid + t * 128]; s += v[t]; s2 += v[t] * v[t]; }
    __shared__ float sa[128], sb[128];
    sa[tid] = s; sb[tid] = s2; __syncthreads();
    for (int o = 64; o > 0; o >>= 1) { if (tid < o) { sa[tid] += sa[tid+o]; sb[tid] += sb[tid+o]; } __syncthreads(); }
    const float mean = sa[0] * (1.0f / DM);
    const float var  = sb[0] * (1.0f / DM) - mean * mean;
    const float rs   = rsqrtf(var + 1e-5f);
    float* orow = out + (size_t)row * DM;
#pragma unroll
    for (int t = 0; t < 4; t++) {
        const int c = tid + t * 128;
        orow[c] = (v[t] - mean) * rs * g[c] + bt[c];
    }
}

// ---------------------------------------------------------------------------
// Misc kernels
// ---------------------------------------------------------------------------
__global__ void embed_k(const int* __restrict__ trg, const float* __restrict__ emb,
                        float* __restrict__ x)
{
    const int total = MROWS * (DM / 4);
    for (int idx = blockIdx.x * blockDim.x + threadIdx.x; idx < total; idx += gridDim.x * blockDim.x) {
        const int row = idx >> 7, c = idx & 127;
        ((float4*)x)[idx] = ((const float4*)emb)[(size_t)trg[row] * 128 + c];
    }
}

__global__ void kvbuild_k(const float* __restrict__ cm, const float* __restrict__ mem,
                          const float* __restrict__ x, float* __restrict__ kv)
{
    const int row = blockIdx.x;           // 0..NB*KVN-1
    const int b = row / KVN, p = row % KVN;
    const float* src;
    if (p < CMEMN)            src = cm  + ((size_t)b * CMEMN + p) * DM;
    else if (p < CMEMN + MEMN) src = mem + ((size_t)b * MEMN + (p - CMEMN)) * DM;
    else                       src = x   + ((size_t)b * SQ + (p - CMEMN - MEMN)) * DM;
    ((float4*)(kv + (size_t)row * DM))[threadIdx.x] = ((const float4*)src)[threadIdx.x];
}

// transpose conv_w (NL, o, d, r) -> wc[layer][k=r*512+d][o]
__global__ void convwT_k(const float* __restrict__ cw, float* __restrict__ wc)
{
    const int total = NLAYERS * RRATIO * DM * DM;
    for (int idx = blockIdx.x * blockDim.x + threadIdx.x; idx < total; idx += gridDim.x * blockDim.x) {
        const int layer = idx / (RRATIO * DM * DM);
        const int rem   = idx % (RRATIO * DM * DM);
        const int k = rem / DM, o = rem % DM;
        wc[idx] = cw[(size_t)layer * RRATIO * DM * DM + (size_t)o * (RRATIO * DM) + (k & 511) * 4 + (k >> 9)];
    }
}

__global__ __launch_bounds__(256) void mse_k(const float* __restrict__ a,
                                             const float* __restrict__ b,
                                             float* __restrict__ part)
{
    __shared__ float sh[256];
    float s = 0.f;
    for (int idx = blockIdx.x * 256 + threadIdx.x; idx < MROWS * DM; idx += 128 * 256) {
        const float d = a[idx] - b[idx];
        s += d * d;
    }
    sh[threadIdx.x] = s; __syncthreads();
    for (int o = 128; o > 0; o >>= 1) { if (threadIdx.x < o) sh[threadIdx.x] += sh[threadIdx.x + o]; __syncthreads(); }
    if (threadIdx.x == 0) part[blockIdx.x] = sh[0];
}

__global__ void copyout_k(const float* __restrict__ x, float* __restrict__ out)
{
    const int total = MROWS * (DM / 4);
    for (int idx = blockIdx.x * blockDim.x + threadIdx.x; idx < total; idx += gridDim.x * blockDim.x)
        ((float4*)out)[idx] = ((const float4*)x)[idx];
}

__global__ __launch_bounds__(128) void loss_k(const float* __restrict__ part,
                                              float* __restrict__ out, int out_size)
{
    __shared__ float sh[128];
    float s = 0.f;
    for (int j = threadIdx.x; j < NLAYERS * 128; j += 128) s += part[j];
    sh[threadIdx.x] = s; __syncthreads();
    for (int o = 64; o > 0; o >>= 1) { if (threadIdx.x < o) sh[threadIdx.x] += sh[threadIdx.x + o]; __syncthreads(); }
    if (threadIdx.x == 0 && out_size > MROWS * DM)
        out[MROWS * DM] = sh[0] * (1.0f / ((float)(MROWS * DM) * (float)NLAYERS));
}

// ---------------------------------------------------------------------------
// Host driver (graph-capturable: kernel launches only)
// ---------------------------------------------------------------------------
extern "C" void kernel_launch(void* const* d_in, const int* in_sizes, int n_in,
                              void* d_out, int out_size)
{
    (void)in_sizes; (void)n_in;
    const int*   trg     = (const int*)  d_in[0];
    const float* latent  = (const float*)d_in[3];
    const float* mems    = (const float*)d_in[4];
    const float* cmems   = (const float*)d_in[5];
    const float* pos_emb = (const float*)d_in[6];
    const float* embed   = (const float*)d_in[7];
    const float* W_self  = (const float*)d_in[8];
    const float* ln1_g   = (const float*)d_in[9];
    const float* ln1_b   = (const float*)d_in[10];
    const float* conv_w  = (const float*)d_in[11];
    const float* conv_b  = (const float*)d_in[12];
    const float* W_src   = (const float*)d_in[13];
    const float* ln2_g   = (const float*)d_in[14];
    const float* ln2_b   = (const float*)d_in[15];
    const float* w1      = (const float*)d_in[16];
    const float* b1      = (const float*)d_in[17];
    const float* w2      = (const float*)d_in[18];
    const float* b2      = (const float*)d_in[19];

    float *x,*kv,*q,*k,*v,*dots,*pos,*ao,*t1,*t2,*cm,*kcm,*vcm,*y,*ff,*wc,*part;
    cudaGetSymbolAddress((void**)&x,   g_x);
    cudaGetSymbolAddress((void**)&kv,  g_kv);
    cudaGetSymbolAddress((void**)&q,   g_q);
    cudaGetSymbolAddress((void**)&k,   g_k);
    cudaGetSymbolAddress((void**)&v,   g_v);
    cudaGetSymbolAddress((void**)&dots,g_dots);
    cudaGetSymbolAddress((void**)&pos, g_pos);
    cudaGetSymbolAddress((void**)&ao,  g_ao);
    cudaGetSymbolAddress((void**)&t1,  g_t1);
    cudaGetSymbolAddress((void**)&t2,  g_t2);
    cudaGetSymbolAddress((void**)&cm,  g_cm);
    cudaGetSymbolAddress((void**)&kcm, g_kcm);
    cudaGetSymbolAddress((void**)&vcm, g_vcm);
    cudaGetSymbolAddress((void**)&y,   g_y);
    cudaGetSymbolAddress((void**)&ff,  g_ff);
    cudaGetSymbolAddress((void**)&wc,  g_wc);
    cudaGetSymbolAddress((void**)&part,g_part);

    embed_k<<<256, 256>>>(trg, embed, x);
    convwT_k<<<2048, 256>>>(conv_w, wc);

    for (int i = 0; i < NLAYERS; i++) {
        const float* Wq  = W_self + ((size_t)i * 4 + 0) * DM * DM;
        const float* Wk  = W_self + ((size_t)i * 4 + 1) * DM * DM;
        const float* Wv  = W_self + ((size_t)i * 4 + 2) * DM * DM;
        const float* Wo  = W_self + ((size_t)i * 4 + 3) * DM * DM;
        const float* Wq2 = W_src  + ((size_t)i * 4 + 0) * DM * DM;
        const float* Wk2 = W_src  + ((size_t)i * 4 + 1) * DM * DM;
        const float* Wv2 = W_src  + ((size_t)i * 4 + 2) * DM * DM;
        const float* Wo2 = W_src  + ((size_t)i * 4 + 3) * DM * DM;
        const float* mems_i  = mems  + (size_t)i * NB * MEMN * DM;
        const float* cmems_i = cmems + (size_t)i * NB * CMEMN * DM;

        // ---- self attention with compressed + regular memory ----
        kvbuild_k<<<NB * KVN, 128>>>(cmems_i, mems_i, x, kv);
        sgemm_k<0><<<dim3(8, 16), 256>>>(x,  Wq, q, MROWS,    DM, DM, nullptr, nullptr);
        sgemm_k<0><<<dim3(8, 36), 256>>>(kv, Wk, k, NB * KVN, DM, DM, nullptr, nullptr);
        sgemm_k<0><<<dim3(8, 36), 256>>>(kv, Wv, v, NB * KVN, DM, DM, nullptr, nullptr);
        scores_k<<<dim3(18, 8, 32), 256>>>(q, k,       dots, KVN, DM, (long)KVN * DM, 64,             0.125f);
        scores_k<<<dim3(18, 8, 32), 256>>>(q, pos_emb, pos,  KVN, DH, 0,              (long)KVN * DH, 8.0f);
        softmax_k<<<dim3(SQ, 32), 128>>>(dots, pos, KVN, 1);
        av_k<<<dim3(1, 8, 32), 256>>>(dots, v, ao, KVN);
        sgemm_k<1><<<dim3(8, 16), 256>>>(ao, Wo, y, MROWS, DM, DM, nullptr, x);  // + residual x
        ln_k<<<MROWS, 128>>>(y, ln1_g + i * DM, ln1_b + i * DM, x);              // x = a

        // ---- conv compress (as GEMM) ----
        sgemm_k<2><<<dim3(8, 4), 256>>>(mems_i, wc + (size_t)i * RRATIO * DM * DM,
                                        cm, NB * CMEMN, DM, RRATIO * DM, conv_b + i * DM, nullptr);

        // ---- reconstruction attention loss ----
        sgemm_k<0><<<dim3(8, 16), 256>>>(x,      Wq, q, MROWS, DM, DM, nullptr, nullptr);
        sgemm_k<0><<<dim3(8, 16), 256>>>(mems_i, Wk, k, MROWS, DM, DM, nullptr, nullptr);
        sgemm_k<0><<<dim3(8, 16), 256>>>(mems_i, Wv, v, MROWS, DM, DM, nullptr, nullptr);
        scores_k<<<dim3(8, 8, 32), 256>>>(q, k, dots, MEMN, DM, (long)MEMN * DM, 64, 0.125f);
        softmax_k<<<dim3(SQ, 32), 128>>>(dots, pos, MEMN, 0);
        av_k<<<dim3(1, 8, 32), 256>>>(dots, v, t1, MEMN);
        sgemm_k<0><<<dim3(8, 4), 256>>>(cm, Wk, kcm, NB * CMEMN, DM, DM, nullptr, nullptr);
        sgemm_k<0><<<dim3(8, 4), 256>>>(cm, Wv, vcm, NB * CMEMN, DM, DM, nullptr, nullptr);
        scores_k<<<dim3(2, 8, 32), 256>>>(q, kcm, dots, CMEMN, DM, (long)CMEMN * DM, 64, 0.125f);
        softmax_k<<<dim3(SQ, 32), 128>>>(dots, pos, CMEMN, 0);
        av_k<<<dim3(1, 8, 32), 256>>>(dots, vcm, t2, CMEMN);
        mse_k<<<128, 256>>>(t1, t2, part + i * 128);

        // ---- cross attention to latent (no residual) ----
        sgemm_k<0><<<dim3(8, 16), 256>>>(x,      Wq2, q, MROWS,     DM, DM, nullptr, nullptr);
        sgemm_k<0><<<dim3(8, 8),  256>>>(latent, Wk2, k, NB * LLAT, DM, DM, nullptr, nullptr);
        sgemm_k<0><<<dim3(8, 8),  256>>>(latent, Wv2, v, NB * LLAT, DM, DM, nullptr, nullptr);
        scores_k<<<dim3(4, 8, 32), 256>>>(q, k, dots, LLAT, DM, (long)LLAT * DM, 64, 0.125f);
        softmax_k<<<dim3(SQ, 32), 128>>>(dots, pos, LLAT, 0);
        av_k<<<dim3(1, 8, 32), 256>>>(dots, v, ao, LLAT);
        sgemm_k<0><<<dim3(8, 16), 256>>>(ao, Wo2, x, MROWS, DM, DM, nullptr, nullptr);  // x replaced

        // ---- feed-forward ----
        ln_k<<<MROWS, 128>>>(x, ln2_g + i * DM, ln2_b + i * DM, y);
        sgemm_k<3><<<dim3(32, 16), 256>>>(y, w1 + (size_t)i * DM * FFD, ff,
                                          MROWS, FFD, DM, b1 + (size_t)i * FFD, nullptr);
        sgemm_k<4><<<dim3(8, 16), 256>>>(ff, w2 + (size_t)i * FFD * DM, x,
                                         MROWS, DM, FFD, b2 + i * DM, x);
    }

    copyout_k<<<512, 256>>>(x, (float*)d_out);
    loss_k<<<1, 128>>>(part, (float*)d_out, out_size);
}

// round 6
// speedup vs baseline: 1.5427x; 1.5427x over previous
#include <cuda_runtime.h>
#include <math.h>
#include <stdint.h>

// ---------------------------------------------------------------------------
// Problem constants
// ---------------------------------------------------------------------------
#define NLAYERS 4
#define NB      4
#define SQ      512
#define DM      512
#define NH      8
#define DH      64
#define MEMN    512
#define CMEMN   128
#define RRATIO  4
#define LLAT    256
#define FFD     2048
#define KVN     (CMEMN + MEMN + SQ)   // 1152
#define MROWS   (NB * SQ)             // 2048

// ---------------------------------------------------------------------------
// Scratch (device globals)
// ---------------------------------------------------------------------------
__device__ float g_x  [MROWS * DM];
__device__ float g_kv [NB * KVN * DM];
__device__ float g_q  [MROWS * DM];
__device__ float g_k  [NB * KVN * DM];
__device__ float g_v  [NB * KVN * DM];
__device__ float g_dots[(size_t)NB * NH * SQ * KVN];
__device__ float g_pos [(size_t)NB * NH * SQ * KVN];
__device__ float g_ao [MROWS * DM];
__device__ float g_t1 [MROWS * DM];
__device__ float g_t2 [MROWS * DM];
__device__ float g_cm [NB * CMEMN * DM];
__device__ float g_kcm[NB * CMEMN * DM];
__device__ float g_vcm[NB * CMEMN * DM];
__device__ float g_y  [MROWS * DM];
__device__ float g_ff [MROWS * FFD];
__device__ float g_wc [NLAYERS * RRATIO * DM * DM];
__device__ float g_sk [4 * 1024 * 1024];          // split-K partials
__device__ float g_part[NLAYERS * 128];

// ---------------------------------------------------------------------------
// Packed fp32x2 helpers (Blackwell FFMA2)
// ---------------------------------------------------------------------------
__device__ __forceinline__ unsigned long long pk2(float lo, float hi) {
    unsigned long long r;
    asm("mov.b64 %0, {%1,%2};" : "=l"(r) : "f"(lo), "f"(hi));
    return r;
}
__device__ __forceinline__ void upk2(unsigned long long v, float& lo, float& hi) {
    asm("mov.b64 {%0,%1}, %2;" : "=f"(lo), "=f"(hi) : "l"(v));
}
__device__ __forceinline__ void fma2(unsigned long long& d, unsigned long long a,
                                     unsigned long long b) {
    asm("fma.rn.f32x2 %0, %1, %2, %0;" : "+l"(d) : "l"(a), "l"(b));
}

// ---------------------------------------------------------------------------
// GEMM core: C[M,N] = A[M,K(full stride)] @ B[K,N] over k in [kBeg,kEnd)
// BM=128, BN=64, BK=16, 256 threads, 8x4 outputs/thread via 4x4 f32x2 accs.
// Double-buffered smem, register prefetch, one sync per K-tile.
// epi: 0 none, 1 +resid, 2 +bias, 3 gelu(.+bias), 4 +bias+resid
// ---------------------------------------------------------------------------
__device__ __forceinline__ void gemm_body(
    const float* __restrict__ A, const float* __restrict__ Bw, float* __restrict__ C,
    int N, int K, int kBeg, int kEnd,
    int epi, const float* __restrict__ bias, const float* __restrict__ resid)
{
    __shared__ __align__(16) float As[2][16][132];
    __shared__ __align__(16) float Bs[2][16][64];
    const int tid  = threadIdx.x;
    const int tx   = tid & 15, ty = tid >> 4;
    const int row0 = blockIdx.y * 128, col0 = blockIdx.x * 64;
    const int ar   = tid >> 2,  ak = (tid & 3) << 2;
    const int br   = tid >> 4,  bc = (tid & 15) << 2;
    const float* Ag = A + (size_t)row0 * K + kBeg;
    const float* Bg = Bw + (size_t)kBeg * N + col0;

    unsigned long long acc[4][4];
#pragma unroll
    for (int m = 0; m < 4; m++)
#pragma unroll
        for (int n = 0; n < 4; n++) acc[m][n] = 0ull;

    const int nk = (kEnd - kBeg) >> 4;
    float4 a0 = *(const float4*)(Ag + (size_t)ar        * K + ak);
    float4 a1 = *(const float4*)(Ag + (size_t)(ar + 64) * K + ak);
    float4 b0 = *(const float4*)(Bg + (size_t)br * N + bc);
    As[0][ak+0][ar]    = a0.x; As[0][ak+1][ar]    = a0.y; As[0][ak+2][ar]    = a0.z; As[0][ak+3][ar]    = a0.w;
    As[0][ak+0][ar+64] = a1.x; As[0][ak+1][ar+64] = a1.y; As[0][ak+2][ar+64] = a1.z; As[0][ak+3][ar+64] = a1.w;
    *(float4*)&Bs[0][br][bc] = b0;
    __syncthreads();

    int buf = 0;
    for (int t = 0; t < nk; t++) {
        const bool more = (t + 1 < nk);
        if (more) {
            const float* Ag2 = Ag + (t + 1) * 16;
            a0 = *(const float4*)(Ag2 + (size_t)ar        * K + ak);
            a1 = *(const float4*)(Ag2 + (size_t)(ar + 64) * K + ak);
            b0 = *(const float4*)(Bg + (size_t)((t + 1) * 16 + br) * N + bc);
        }
#pragma unroll
        for (int k = 0; k < 16; k++) {
            float4 av0 = *(const float4*)&As[buf][k][ty*8];
            float4 av1 = *(const float4*)&As[buf][k][ty*8 + 4];
            float4 bv  = *(const float4*)&Bs[buf][k][tx*4];
            unsigned long long am[4] = { pk2(av0.x, av0.y), pk2(av0.z, av0.w),
                                         pk2(av1.x, av1.y), pk2(av1.z, av1.w) };
            unsigned long long bd[4] = { pk2(bv.x, bv.x), pk2(bv.y, bv.y),
                                         pk2(bv.z, bv.z), pk2(bv.w, bv.w) };
#pragma unroll
            for (int m = 0; m < 4; m++)
#pragma unroll
                for (int n = 0; n < 4; n++) fma2(acc[m][n], am[m], bd[n]);
        }
        if (more) {
            const int nb = buf ^ 1;
            As[nb][ak+0][ar]    = a0.x; As[nb][ak+1][ar]    = a0.y; As[nb][ak+2][ar]    = a0.z; As[nb][ak+3][ar]    = a0.w;
            As[nb][ak+0][ar+64] = a1.x; As[nb][ak+1][ar+64] = a1.y; As[nb][ak+2][ar+64] = a1.z; As[nb][ak+3][ar+64] = a1.w;
            *(float4*)&Bs[nb][br][bc] = b0;
        }
        __syncthreads();
        buf ^= 1;
    }

    const int c0 = col0 + tx * 4;
#pragma unroll
    for (int m2 = 0; m2 < 4; m2++) {
        const int r = row0 + ty * 8 + m2 * 2;
        float lo[4], hi[4];
#pragma unroll
        for (int n = 0; n < 4; n++) upk2(acc[m2][n], lo[n], hi[n]);
        if (epi == 2 || epi == 3 || epi == 4) {
            float4 bb = *(const float4*)(bias + c0);
            lo[0]+=bb.x; lo[1]+=bb.y; lo[2]+=bb.z; lo[3]+=bb.w;
            hi[0]+=bb.x; hi[1]+=bb.y; hi[2]+=bb.z; hi[3]+=bb.w;
        }
        if (epi == 3) {
#pragma unroll
            for (int n = 0; n < 4; n++) {
                lo[n] = 0.5f * lo[n] * (1.0f + erff(lo[n] * 0.70710678118654752440f));
                hi[n] = 0.5f * hi[n] * (1.0f + erff(hi[n] * 0.70710678118654752440f));
            }
        }
        if (epi == 1 || epi == 4) {
            float4 r0 = *(const float4*)(resid + (size_t)r * N + c0);
            float4 r1 = *(const float4*)(resid + (size_t)(r + 1) * N + c0);
            lo[0]+=r0.x; lo[1]+=r0.y; lo[2]+=r0.z; lo[3]+=r0.w;
            hi[0]+=r1.x; hi[1]+=r1.y; hi[2]+=r1.z; hi[3]+=r1.w;
        }
        *(float4*)(C + (size_t)r       * N + c0) = make_float4(lo[0], lo[1], lo[2], lo[3]);
        *(float4*)(C + (size_t)(r + 1) * N + c0) = make_float4(hi[0], hi[1], hi[2], hi[3]);
    }
}

// z-batched SGEMM (up to 3 problems sharing N, K; early-exit past M_z)
__global__ __launch_bounds__(256, 2) void sgemm_k(
    const float* A0, const float* B0, float* C0, int M0,
    const float* A1, const float* B1, float* C1, int M1,
    const float* A2, const float* B2, float* C2, int M2,
    int N, int K, int epi, const float* bias, const float* resid)
{
    const int z = blockIdx.z;
    const float* A  = (z == 0) ? A0 : (z == 1) ? A1 : A2;
    const float* Bw = (z == 0) ? B0 : (z == 1) ? B1 : B2;
    float*       C  = (z == 0) ? C0 : (z == 1) ? C1 : C2;
    const int    M  = (z == 0) ? M0 : (z == 1) ? M1 : M2;
    if (blockIdx.y * 128 >= M) return;
    gemm_body(A, Bw, C, N, K, 0, K, epi, bias, resid);
}

// split-K SGEMM: z = K-chunk, writes partials Cpart[z][M][N]
__global__ __launch_bounds__(256, 2) void sgemm_splitk_k(
    const float* A, const float* Bw, float* Cpart, int M, int N, int K, int KC)
{
    const int z = blockIdx.z;
    gemm_body(A, Bw, Cpart + (size_t)z * M * N, N, K, z * KC, z * KC + KC,
              0, nullptr, nullptr);
}

// split-K reduce + epilogue (deterministic order)
__global__ void redk_k(const float* __restrict__ parts, int nparts, int total, int N,
                       int epi, const float* __restrict__ bias,
                       const float* __restrict__ resid, float* __restrict__ out)
{
    for (int idx = blockIdx.x * blockDim.x + threadIdx.x; idx < total;
         idx += gridDim.x * blockDim.x) {
        float s = parts[idx];
        for (int p = 1; p < nparts; p++) s += parts[(size_t)p * total + idx];
        const int c = idx % N;
        if (epi == 2) s += bias[c];
        else if (epi == 4) s += bias[c] + resid[idx];
        out[idx] = s;
    }
}

// ---------------------------------------------------------------------------
// Attention scores: out[bh,i,j] = scale * sum_d Q[b,i,h,d] * Kb[...,j,d]
// ---------------------------------------------------------------------------
__global__ __launch_bounds__(256, 2) void scores_k(
    const float* __restrict__ Q, const float* __restrict__ Kb,
    float* __restrict__ out, int L, int ldb, long bSB, long bSH, float scale)
{
    __shared__ __align__(16) float Qs[64][68];  // [d][i]
    __shared__ __align__(16) float Ks[64][68];  // [d][j]
    const int bh = blockIdx.z, b = bh >> 3, h = bh & 7;
    const int i0 = blockIdx.y * 64, j0 = blockIdx.x * 64;
    const float* Qg = Q + ((size_t)(b * SQ + i0)) * DM + h * DH;
    const float* Kg = Kb + (size_t)b * bSB + (size_t)h * bSH + (size_t)j0 * ldb;
    const int tid = threadIdx.x;
    const int rr = tid >> 4, c4 = (tid & 15) << 2;
#pragma unroll
    for (int s = 0; s < 4; s++) {
        const int r = rr + s * 16;
        float4 qv = *(const float4*)(Qg + (size_t)r * DM + c4);
        Qs[c4+0][r] = qv.x; Qs[c4+1][r] = qv.y; Qs[c4+2][r] = qv.z; Qs[c4+3][r] = qv.w;
        float4 kv2 = *(const float4*)(Kg + (size_t)r * ldb + c4);
        Ks[c4+0][r] = kv2.x; Ks[c4+1][r] = kv2.y; Ks[c4+2][r] = kv2.z; Ks[c4+3][r] = kv2.w;
    }
    __syncthreads();
    const int tx = tid & 15, ty = tid >> 4;
    unsigned long long acc[2][4];
#pragma unroll
    for (int m = 0; m < 2; m++)
#pragma unroll
        for (int n = 0; n < 4; n++) acc[m][n] = 0ull;
#pragma unroll
    for (int d = 0; d < 64; d++) {
        float4 av = *(const float4*)&Qs[d][ty*4];
        float4 bv = *(const float4*)&Ks[d][tx*4];
        unsigned long long am[2] = { pk2(av.x, av.y), pk2(av.z, av.w) };
        unsigned long long bd[4] = { pk2(bv.x, bv.x), pk2(bv.y, bv.y),
                                     pk2(bv.z, bv.z), pk2(bv.w, bv.w) };
#pragma unroll
        for (int m = 0; m < 2; m++)
#pragma unroll
            for (int n = 0; n < 4; n++) fma2(acc[m][n], am[m], bd[n]);
    }
    float* Og = out + ((long)bh * SQ + i0) * (long)L + j0 + tx * 4;
#pragma unroll
    for (int m2 = 0; m2 < 2; m2++) {
        float lo[4], hi[4];
#pragma unroll
        for (int n = 0; n < 4; n++) upk2(acc[m2][n], lo[n], hi[n]);
        *(float4*)(Og + (long)(ty*4 + 2*m2)     * L) =
            make_float4(lo[0]*scale, lo[1]*scale, lo[2]*scale, lo[3]*scale);
        *(float4*)(Og + (long)(ty*4 + 2*m2 + 1) * L) =
            make_float4(hi[0]*scale, hi[1]*scale, hi[2]*scale, hi[3]*scale);
    }
}

// ---------------------------------------------------------------------------
// AV: out[b,i,h,d] = sum_j P[bh,i,j] * V[b,j,h,d]
// ---------------------------------------------------------------------------
__global__ __launch_bounds__(256, 2) void av_k(
    const float* __restrict__ P, const float* __restrict__ V,
    float* __restrict__ out, int L)
{
    __shared__ __align__(16) float Ps[64][68];  // [j][i]
    __shared__ __align__(16) float Vs[64][68];  // [j][d]
    const int bh = blockIdx.z, b = bh >> 3, h = bh & 7;
    const int i0 = blockIdx.y * 64;
    const float* Pg = P + ((long)bh * SQ + i0) * (long)L;
    const float* Vg = V + (size_t)b * L * DM + h * DH;
    const int tid = threadIdx.x;
    const int rr = tid >> 4, c4 = (tid & 15) << 2;
    const int tx = tid & 15, ty = tid >> 4;
    unsigned long long acc[2][4];
#pragma unroll
    for (int m = 0; m < 2; m++)
#pragma unroll
        for (int n = 0; n < 4; n++) acc[m][n] = 0ull;
    for (int j0 = 0; j0 < L; j0 += 64) {
#pragma unroll
        for (int s = 0; s < 4; s++) {
            const int r = rr + s * 16;
            float4 pv = *(const float4*)(Pg + (long)r * L + j0 + c4);
            Ps[c4+0][r] = pv.x; Ps[c4+1][r] = pv.y; Ps[c4+2][r] = pv.z; Ps[c4+3][r] = pv.w;
            float4 vv = *(const float4*)(Vg + (size_t)(j0 + r) * DM + c4);
            *(float4*)&Vs[r][c4] = vv;
        }
        __syncthreads();
#pragma unroll
        for (int j = 0; j < 64; j++) {
            float4 av = *(const float4*)&Ps[j][ty*4];
            float4 bv = *(const float4*)&Vs[j][tx*4];
            unsigned long long am[2] = { pk2(av.x, av.y), pk2(av.z, av.w) };
            unsigned long long bd[4] = { pk2(bv.x, bv.x), pk2(bv.y, bv.y),
                                         pk2(bv.z, bv.z), pk2(bv.w, bv.w) };
#pragma unroll
            for (int m = 0; m < 2; m++)
#pragma unroll
                for (int n = 0; n < 4; n++) fma2(acc[m][n], am[m], bd[n]);
        }
        __syncthreads();
    }
    float* Og = out + ((size_t)(b * SQ + i0)) * DM + h * DH + tx * 4;
#pragma unroll
    for (int m2 = 0; m2 < 2; m2++) {
        float lo[4], hi[4];
#pragma unroll
        for (int n = 0; n < 4; n++) upk2(acc[m2][n], lo[n], hi[n]);
        *(float4*)(Og + (size_t)(ty*4 + 2*m2)     * DM) = make_float4(lo[0], lo[1], lo[2], lo[3]);
        *(float4*)(Og + (size_t)(ty*4 + 2*m2 + 1) * DM) = make_float4(hi[0], hi[1], hi[2], hi[3]);
    }
}

// ---------------------------------------------------------------------------
// Softmax over row of length L (multiple of 128), optional shifted pos add
// ---------------------------------------------------------------------------
__global__ __launch_bounds__(128) void softmax_k(
    float* __restrict__ dots, const float* __restrict__ posR, int L, int usePos)
{
    const int i = blockIdx.x, bh = blockIdx.y;
    float* row = dots + ((long)bh * SQ + i) * (long)L;
    const float* prow = posR + ((long)bh * SQ + i) * (long)KVN;
    const int tid = threadIdx.x;
    const int nper = L >> 7;
    float vals[9];
    float mx = -1e30f;
    for (int t = 0; t < nper; t++) {
        const int j = tid + t * 128;
        float vv = row[j];
        if (usePos) {
            const int jp = j + (SQ - 1) - i;
            if (jp < KVN) vv += prow[jp];
        }
        vals[t] = vv;
        mx = fmaxf(mx, vv);
    }
    __shared__ float sh[128];
    sh[tid] = mx; __syncthreads();
    for (int o = 64; o > 0; o >>= 1) { if (tid < o) sh[tid] = fmaxf(sh[tid], sh[tid + o]); __syncthreads(); }
    mx = sh[0]; __syncthreads();
    float s = 0.f;
    for (int t = 0; t < nper; t++) { vals[t] = __expf(vals[t] - mx); s += vals[t]; }
    sh[tid] = s; __syncthreads();
    for (int o = 64; o > 0; o >>= 1) { if (tid < o) sh[tid] += sh[tid + o]; __syncthreads(); }
    const float inv = 1.0f / sh[0];
    for (int t = 0; t < nper; t++) row[tid + t * 128] = vals[t] * inv;
}

// ---------------------------------------------------------------------------
// LayerNorm over D=512
// ---------------------------------------------------------------------------
__global__ __launch_bounds__(128) void ln_k(
    const float* __restrict__ x, const float* __restrict__ g,
    const float* __restrict__ bt, float* __restrict__ out)
{
    const int row = blockIdx.x, tid = threadIdx.x;
    const float* xr = x + (size_t)row * DM;
    float v[4]; float s = 0.f, s2 = 0.f;
#pragma unroll
    for (int t = 0; t < 4; t++) { v[t] = xr[tid + t * 128]; s += v[t]; s2 += v[t] * v[t]; }
    __shared__ float sa[128], sb[128];
    sa[tid] = s; sb[tid] = s2; __syncthreads();
    for (int o = 64; o > 0; o >>= 1) { if (tid < o) { sa[tid] += sa[tid+o]; sb[tid] += sb[tid+o]; } __syncthreads(); }
    const float mean = sa[0] * (1.0f / DM);
    const float var  = sb[0] * (1.0f / DM) - mean * mean;
    const float rs   = rsqrtf(var + 1e-5f);
    float* orow = out + (size_t)row * DM;
#pragma unroll
    for (int t = 0; t < 4; t++) {
        const int c = tid + t * 128;
        orow[c] = (v[t] - mean) * rs * g[c] + bt[c];
    }
}

// ---------------------------------------------------------------------------
// Misc kernels
// ---------------------------------------------------------------------------
__global__ void embed_k(const int* __restrict__ trg, const float* __restrict__ emb,
                        float* __restrict__ x)
{
    const int total = MROWS * (DM / 4);
    for (int idx = blockIdx.x * blockDim.x + threadIdx.x; idx < total; idx += gridDim.x * blockDim.x) {
        const int row = idx >> 7, c = idx & 127;
        ((float4*)x)[idx] = ((const float4*)emb)[(size_t)trg[row] * 128 + c];
    }
}

__global__ void kvbuild_k(const float* __restrict__ cm, const float* __restrict__ mem,
                          const float* __restrict__ x, float* __restrict__ kv)
{
    const int row = blockIdx.x;
    const int b = row / KVN, p = row % KVN;
    const float* src;
    if (p < CMEMN)             src = cm  + ((size_t)b * CMEMN + p) * DM;
    else if (p < CMEMN + MEMN) src = mem + ((size_t)b * MEMN + (p - CMEMN)) * DM;
    else                       src = x   + ((size_t)b * SQ + (p - CMEMN - MEMN)) * DM;
    ((float4*)(kv + (size_t)row * DM))[threadIdx.x] = ((const float4*)src)[threadIdx.x];
}

// transpose conv_w (NL, o, d, r) -> wc[layer][k=r*512+d][o]
__global__ void convwT_k(const float* __restrict__ cw, float* __restrict__ wc)
{
    const int total = NLAYERS * RRATIO * DM * DM;
    for (int idx = blockIdx.x * blockDim.x + threadIdx.x; idx < total; idx += gridDim.x * blockDim.x) {
        const int layer = idx / (RRATIO * DM * DM);
        const int rem   = idx % (RRATIO * DM * DM);
        const int k = rem / DM, o = rem % DM;
        wc[idx] = cw[(size_t)layer * RRATIO * DM * DM + (size_t)o * (RRATIO * DM) + (k & 511) * 4 + (k >> 9)];
    }
}

__global__ __launch_bounds__(256) void mse_k(const float* __restrict__ a,
                                             const float* __restrict__ b,
                                             float* __restrict__ part)
{
    __shared__ float sh[256];
    float s = 0.f;
    for (int idx = blockIdx.x * 256 + threadIdx.x; idx < MROWS * DM; idx += 128 * 256) {
        const float d = a[idx] - b[idx];
        s += d * d;
    }
    sh[threadIdx.x] = s; __syncthreads();
    for (int o = 128; o > 0; o >>= 1) { if (threadIdx.x < o) sh[threadIdx.x] += sh[threadIdx.x + o]; __syncthreads(); }
    if (threadIdx.x == 0) part[blockIdx.x] = sh[0];
}

__global__ void copyout_k(const float* __restrict__ x, float* __restrict__ out)
{
    const int total = MROWS * (DM / 4);
    for (int idx = blockIdx.x * blockDim.x + threadIdx.x; idx < total; idx += gridDim.x * blockDim.x)
        ((float4*)out)[idx] = ((const float4*)x)[idx];
}

__global__ __launch_bounds__(128) void loss_k(const float* __restrict__ part,
                                              float* __restrict__ out, int out_size)
{
    __shared__ float sh[128];
    float s = 0.f;
    for (int j = threadIdx.x; j < NLAYERS * 128; j += 128) s += part[j];
    sh[threadIdx.x] = s; __syncthreads();
    for (int o = 64; o > 0; o >>= 1) { if (threadIdx.x < o) sh[threadIdx.x] += sh[threadIdx.x + o]; __syncthreads(); }
    if (threadIdx.x == 0 && out_size > MROWS * DM)
        out[MROWS * DM] = sh[0] * (1.0f / ((float)(MROWS * DM) * (float)NLAYERS));
}

// ---------------------------------------------------------------------------
// Host driver
// ---------------------------------------------------------------------------
extern "C" void kernel_launch(void* const* d_in, const int* in_sizes, int n_in,
                              void* d_out, int out_size)
{
    (void)in_sizes; (void)n_in;
    const int*   trg     = (const int*)  d_in[0];
    const float* latent  = (const float*)d_in[3];
    const float* mems    = (const float*)d_in[4];
    const float* cmems   = (const float*)d_in[5];
    const float* pos_emb = (const float*)d_in[6];
    const float* embed   = (const float*)d_in[7];
    const float* W_self  = (const float*)d_in[8];
    const float* ln1_g   = (const float*)d_in[9];
    const float* ln1_b   = (const float*)d_in[10];
    const float* conv_w  = (const float*)d_in[11];
    const float* conv_b  = (const float*)d_in[12];
    const float* W_src   = (const float*)d_in[13];
    const float* ln2_g   = (const float*)d_in[14];
    const float* ln2_b   = (const float*)d_in[15];
    const float* w1      = (const float*)d_in[16];
    const float* b1      = (const float*)d_in[17];
    const float* w2      = (const float*)d_in[18];
    const float* b2      = (const float*)d_in[19];

    float *x,*kv,*q,*k,*v,*dots,*pos,*ao,*t1,*t2,*cm,*kcm,*vcm,*y,*ff,*wc,*sk,*part;
    cudaGetSymbolAddress((void**)&x,   g_x);
    cudaGetSymbolAddress((void**)&kv,  g_kv);
    cudaGetSymbolAddress((void**)&q,   g_q);
    cudaGetSymbolAddress((void**)&k,   g_k);
    cudaGetSymbolAddress((void**)&v,   g_v);
    cudaGetSymbolAddress((void**)&dots,g_dots);
    cudaGetSymbolAddress((void**)&pos, g_pos);
    cudaGetSymbolAddress((void**)&ao,  g_ao);
    cudaGetSymbolAddress((void**)&t1,  g_t1);
    cudaGetSymbolAddress((void**)&t2,  g_t2);
    cudaGetSymbolAddress((void**)&cm,  g_cm);
    cudaGetSymbolAddress((void**)&kcm, g_kcm);
    cudaGetSymbolAddress((void**)&vcm, g_vcm);
    cudaGetSymbolAddress((void**)&y,   g_y);
    cudaGetSymbolAddress((void**)&ff,  g_ff);
    cudaGetSymbolAddress((void**)&wc,  g_wc);
    cudaGetSymbolAddress((void**)&sk,  g_sk);
    cudaGetSymbolAddress((void**)&part,g_part);

    embed_k<<<256, 256>>>(trg, embed, x);
    convwT_k<<<2048, 256>>>(conv_w, wc);

    for (int i = 0; i < NLAYERS; i++) {
        const float* Wq  = W_self + ((size_t)i * 4 + 0) * DM * DM;
        const float* Wk  = W_self + ((size_t)i * 4 + 1) * DM * DM;
        const float* Wv  = W_self + ((size_t)i * 4 + 2) * DM * DM;
        const float* Wo  = W_self + ((size_t)i * 4 + 3) * DM * DM;
        const float* Wq2 = W_src  + ((size_t)i * 4 + 0) * DM * DM;
        const float* Wk2 = W_src  + ((size_t)i * 4 + 1) * DM * DM;
        const float* Wv2 = W_src  + ((size_t)i * 4 + 2) * DM * DM;
        const float* Wo2 = W_src  + ((size_t)i * 4 + 3) * DM * DM;
        const float* mems_i  = mems  + (size_t)i * NB * MEMN * DM;
        const float* cmems_i = cmems + (size_t)i * NB * CMEMN * DM;

        // ---- self attention (batched q/k/v projection) ----
        kvbuild_k<<<NB * KVN, 128>>>(cmems_i, mems_i, x, kv);
        sgemm_k<<<dim3(8, 36, 3), 256>>>(x,  Wq, q, MROWS,
                                         kv, Wk, k, NB * KVN,
                                         kv, Wv, v, NB * KVN,
                                         DM, DM, 0, nullptr, nullptr);
        scores_k<<<dim3(18, 8, 32), 256>>>(q, k,       dots, KVN, DM, (long)KVN * DM, 64,             0.125f);
        scores_k<<<dim3(18, 8, 32), 256>>>(q, pos_emb, pos,  KVN, DH, 0,              (long)KVN * DH, 8.0f);
        softmax_k<<<dim3(SQ, 32), 128>>>(dots, pos, KVN, 1);
        av_k<<<dim3(1, 8, 32), 256>>>(dots, v, ao, KVN);
        sgemm_k<<<dim3(8, 16, 1), 256>>>(ao, Wo, y, MROWS,
                                         nullptr, nullptr, nullptr, 0,
                                         nullptr, nullptr, nullptr, 0,
                                         DM, DM, 1, nullptr, x);
        ln_k<<<MROWS, 128>>>(y, ln1_g + i * DM, ln1_b + i * DM, x);

        // ---- conv compress (GEMM, split-K=4) ----
        sgemm_splitk_k<<<dim3(8, 4, 4), 256>>>(mems_i, wc + (size_t)i * RRATIO * DM * DM,
                                               sk, NB * CMEMN, DM, RRATIO * DM, DM);
        redk_k<<<256, 256>>>(sk, 4, NB * CMEMN * DM, DM, 2, conv_b + i * DM, nullptr, cm);

        // ---- reconstruction attention loss (batched q/k/v) ----
        sgemm_k<<<dim3(8, 16, 3), 256>>>(x,      Wq, q, MROWS,
                                         mems_i, Wk, k, MROWS,
                                         mems_i, Wv, v, MROWS,
                                         DM, DM, 0, nullptr, nullptr);
        scores_k<<<dim3(8, 8, 32), 256>>>(q, k, dots, MEMN, DM, (long)MEMN * DM, 64, 0.125f);
        softmax_k<<<dim3(SQ, 32), 128>>>(dots, pos, MEMN, 0);
        av_k<<<dim3(1, 8, 32), 256>>>(dots, v, t1, MEMN);
        sgemm_k<<<dim3(8, 4, 2), 256>>>(cm, Wk, kcm, NB * CMEMN,
                                        cm, Wv, vcm, NB * CMEMN,
                                        nullptr, nullptr, nullptr, 0,
                                        DM, DM, 0, nullptr, nullptr);
        scores_k<<<dim3(2, 8, 32), 256>>>(q, kcm, dots, CMEMN, DM, (long)CMEMN * DM, 64, 0.125f);
        softmax_k<<<dim3(SQ, 32), 128>>>(dots, pos, CMEMN, 0);
        av_k<<<dim3(1, 8, 32), 256>>>(dots, vcm, t2, CMEMN);
        mse_k<<<128, 256>>>(t1, t2, part + i * 128);

        // ---- cross attention to latent (batched q/k/v) ----
        sgemm_k<<<dim3(8, 16, 3), 256>>>(x,      Wq2, q, MROWS,
                                         latent, Wk2, k, NB * LLAT,
                                         latent, Wv2, v, NB * LLAT,
                                         DM, DM, 0, nullptr, nullptr);
        scores_k<<<dim3(4, 8, 32), 256>>>(q, k, dots, LLAT, DM, (long)LLAT * DM, 64, 0.125f);
        softmax_k<<<dim3(SQ, 32), 128>>>(dots, pos, LLAT, 0);
        av_k<<<dim3(1, 8, 32), 256>>>(dots, v, ao, LLAT);
        sgemm_k<<<dim3(8, 16, 1), 256>>>(ao, Wo2, x, MROWS,
                                         nullptr, nullptr, nullptr, 0,
                                         nullptr, nullptr, nullptr, 0,
                                         DM, DM, 0, nullptr, nullptr);

        // ---- feed-forward ----
        ln_k<<<MROWS, 128>>>(x, ln2_g + i * DM, ln2_b + i * DM, y);
        sgemm_k<<<dim3(32, 16, 1), 256>>>(y, w1 + (size_t)i * DM * FFD, ff, MROWS,
                                          nullptr, nullptr, nullptr, 0,
                                          nullptr, nullptr, nullptr, 0,
                                          FFD, DM, 3, b1 + (size_t)i * FFD, nullptr);
        sgemm_splitk_k<<<dim3(8, 16, 2), 256>>>(ff, w2 + (size_t)i * FFD * DM,
                                                sk, MROWS, DM, FFD, FFD / 2);
        redk_k<<<512, 256>>>(sk, 2, MROWS * DM, DM, 4, b2 + i * DM, x, x);
    }

    copyout_k<<<512, 256>>>(x, (float*)d_out);
    loss_k<<<1, 128>>>(part, (float*)d_out, out_size);
}